// round 6
// baseline (speedup 1.0000x reference)
#include <cuda_runtime.h>
#include <cuda_bf16.h>
#include <cstdint>
#include <cstddef>

// ---------------- problem constants ----------------
#define T_LEN 128
#define BATCH 32
#define HID   1024
#define VOCAB 32000
#define MROWS (T_LEN * BATCH)        // 4096
#define LOGITS_ELEMS ((size_t)MROWS * VOCAB)   // 131072000
#define HIDDEN_ELEMS (2 * BATCH * HID)         // 65536

// ---------------- device scratch (no runtime alloc allowed) ----------------
__device__ float g_x [MROWS * HID];     // layer input / output sequence (16 MB)
__device__ float g_xw[MROWS * HID];     // precomputed input projection  (16 MB)
__device__ float g_ht[2 * HID * BATCH]; // TRANSPOSED ping-pong hidden [2][HID][BATCH]
__device__ int   g_flags[128];          // persistent-kernel grid barrier flags

// =====================================================================
// Embedding gather
// =====================================================================
__global__ __launch_bounds__(256)
void embed_k(const int* __restrict__ idx, const float* __restrict__ emb,
             float* __restrict__ xout)
{
    int row = blockIdx.x;
    int tok = idx[row];
    const float4* s = (const float4*)(emb + (size_t)tok * HID);
    float4* d = (float4*)(xout + (size_t)row * HID);
    d[threadIdx.x] = s[threadIdx.x];
}

// =====================================================================
// tf32 helpers
// =====================================================================
__device__ __forceinline__ float tf32_hi(float v)
{
    uint32_t t;
    asm("cvt.rna.tf32.f32 %0, %1;" : "=r"(t) : "f"(v));
    return __uint_as_float(t);
}
__device__ __forceinline__ void split_cvt(float v, float& hi, float& lo)
{
    hi = tf32_hi(v);
    lo = tf32_hi(v - hi);
}

__device__ __forceinline__ void mma_tf32(float c[4], uint32_t a0, uint32_t a1,
                                         uint32_t a2, uint32_t a3,
                                         uint32_t b0, uint32_t b1)
{
    asm volatile(
        "mma.sync.aligned.m16n8k8.row.col.f32.tf32.tf32.f32 "
        "{%0,%1,%2,%3}, {%4,%5,%6,%7}, {%8,%9}, {%0,%1,%2,%3};"
        : "+f"(c[0]), "+f"(c[1]), "+f"(c[2]), "+f"(c[3])
        : "r"(a0), "r"(a1), "r"(a2), "r"(a3), "r"(b0), "r"(b1));
}

#define BM 128
#define BN 128
#define BK 32
#define SAPAD 132

// =====================================================================
// Single-pass tf32 GEMM (output projection): C = A[M,K] * B[N,K]^T + bias
// =====================================================================
__global__ __launch_bounds__(256)
void gemm_tf32(const float* __restrict__ A, const float* __restrict__ B,
               float* __restrict__ C, const float* __restrict__ bias,
               int M, int N, int K)
{
    __shared__ float As[BK][SAPAD];
    __shared__ float Bs[BK][SAPAD];

    int tid  = threadIdx.x;
    int warp = tid >> 5, lane = tid & 31;
    int wm   = warp >> 2;
    int wn   = warp & 3;
    int gID  = lane >> 2;
    int tig  = lane & 3;

    int rowBase = blockIdx.x * BM;
    int colBase = blockIdx.y * BN;

    int lc4 = tid & 7;
    int lr  = tid >> 3;
    const float* Aload = A + (size_t)(rowBase + lr) * K + lc4 * 4;
    const float* Bload = B + (size_t)(colBase + lr) * K + lc4 * 4;

    float4 aReg[4], bReg[4];

    float acc[4][4][4];
#pragma unroll
    for (int mt = 0; mt < 4; mt++)
#pragma unroll
        for (int nt = 0; nt < 4; nt++)
#pragma unroll
            for (int q = 0; q < 4; q++) acc[mt][nt][q] = 0.f;

    const int NT = K / BK;

#pragma unroll
    for (int i = 0; i < 4; i++) {
        aReg[i] = *(const float4*)(Aload + (size_t)i * 32 * K);
        bReg[i] = *(const float4*)(Bload + (size_t)i * 32 * K);
    }
#pragma unroll
    for (int i = 0; i < 4; i++) {
        int m = lr + i * 32;
        float va[4] = {aReg[i].x, aReg[i].y, aReg[i].z, aReg[i].w};
        float vb[4] = {bReg[i].x, bReg[i].y, bReg[i].z, bReg[i].w};
#pragma unroll
        for (int q = 0; q < 4; q++) {
            As[lc4 * 4 + q][m] = tf32_hi(va[q]);
            Bs[lc4 * 4 + q][m] = tf32_hi(vb[q]);
        }
    }
    __syncthreads();

    for (int kt = 0; kt < NT; kt++) {
        if (kt + 1 < NT) {
            const float* ap = Aload + (size_t)(kt + 1) * BK;
            const float* bp = Bload + (size_t)(kt + 1) * BK;
#pragma unroll
            for (int i = 0; i < 4; i++) {
                aReg[i] = *(const float4*)(ap + (size_t)i * 32 * K);
                bReg[i] = *(const float4*)(bp + (size_t)i * 32 * K);
            }
        }
#pragma unroll
        for (int ks = 0; ks < 4; ks++) {
            int kb = ks * 8;
            uint32_t af[4][4];
#pragma unroll
            for (int mt = 0; mt < 4; mt++) {
                int m0 = wm * 64 + mt * 16 + gID;
                af[mt][0] = __float_as_uint(As[kb + tig    ][m0    ]);
                af[mt][1] = __float_as_uint(As[kb + tig    ][m0 + 8]);
                af[mt][2] = __float_as_uint(As[kb + tig + 4][m0    ]);
                af[mt][3] = __float_as_uint(As[kb + tig + 4][m0 + 8]);
            }
#pragma unroll
            for (int nt = 0; nt < 4; nt++) {
                int n0 = wn * 32 + nt * 8 + gID;
                uint32_t b0 = __float_as_uint(Bs[kb + tig    ][n0]);
                uint32_t b1 = __float_as_uint(Bs[kb + tig + 4][n0]);
#pragma unroll
                for (int mt = 0; mt < 4; mt++)
                    mma_tf32(acc[mt][nt], af[mt][0], af[mt][1], af[mt][2],
                             af[mt][3], b0, b1);
            }
        }
        __syncthreads();
        if (kt + 1 < NT) {
#pragma unroll
            for (int i = 0; i < 4; i++) {
                int m = lr + i * 32;
                float va[4] = {aReg[i].x, aReg[i].y, aReg[i].z, aReg[i].w};
                float vb[4] = {bReg[i].x, bReg[i].y, bReg[i].z, bReg[i].w};
#pragma unroll
                for (int q = 0; q < 4; q++) {
                    As[lc4 * 4 + q][m] = tf32_hi(va[q]);
                    Bs[lc4 * 4 + q][m] = tf32_hi(vb[q]);
                }
            }
            __syncthreads();
        }
    }

#pragma unroll
    for (int mt = 0; mt < 4; mt++) {
#pragma unroll
        for (int nt = 0; nt < 4; nt++) {
            int r0 = rowBase + wm * 64 + mt * 16 + gID;
            int c0 = colBase + wn * 32 + nt * 8 + tig * 2;
            float bi0 = bias ? bias[c0] : 0.f;
            float bi1 = bias ? bias[c0 + 1] : 0.f;
            float* p0 = C + (size_t)r0 * N + c0;
            float* p1 = C + (size_t)(r0 + 8) * N + c0;
            *(float2*)p0 = make_float2(acc[mt][nt][0] + bi0, acc[mt][nt][1] + bi1);
            *(float2*)p1 = make_float2(acc[mt][nt][2] + bi0, acc[mt][nt][3] + bi1);
        }
    }
}

// =====================================================================
// Fused 3-term tf32 split GEMM (near-fp32): C = A*B^T + bias in ONE pass.
// =====================================================================
__global__ __launch_bounds__(256)
void gemm_split3(const float* __restrict__ A, const float* __restrict__ B,
                 float* __restrict__ C, const float* __restrict__ bias,
                 int M, int N, int K)
{
    extern __shared__ float smem[];
    float* Ah = smem;
    float* Al = smem + BK * SAPAD;
    float* Bh = smem + 2 * BK * SAPAD;
    float* Bl = smem + 3 * BK * SAPAD;

    int tid  = threadIdx.x;
    int warp = tid >> 5, lane = tid & 31;
    int wm   = warp >> 2;
    int wn   = warp & 3;
    int gID  = lane >> 2;
    int tig  = lane & 3;

    int rowBase = blockIdx.x * BM;
    int colBase = blockIdx.y * BN;

    int lc4 = tid & 7;
    int lr  = tid >> 3;
    const float* Aload = A + (size_t)(rowBase + lr) * K + lc4 * 4;
    const float* Bload = B + (size_t)(colBase + lr) * K + lc4 * 4;

    float acc[4][4][4];
#pragma unroll
    for (int mt = 0; mt < 4; mt++)
#pragma unroll
        for (int nt = 0; nt < 4; nt++)
#pragma unroll
            for (int q = 0; q < 4; q++) acc[mt][nt][q] = 0.f;

    const int NT = K / BK;

    for (int kt = 0; kt < NT; kt++) {
#pragma unroll
        for (int i = 0; i < 4; i++) {
            float4 va = *(const float4*)(Aload + (size_t)kt * BK + (size_t)i * 32 * K);
            float4 vb = *(const float4*)(Bload + (size_t)kt * BK + (size_t)i * 32 * K);
            int m = lr + i * 32;
            float a4[4] = {va.x, va.y, va.z, va.w};
            float b4[4] = {vb.x, vb.y, vb.z, vb.w};
#pragma unroll
            for (int q = 0; q < 4; q++) {
                float hi, lo;
                split_cvt(a4[q], hi, lo);
                Ah[(lc4 * 4 + q) * SAPAD + m] = hi;
                Al[(lc4 * 4 + q) * SAPAD + m] = lo;
                split_cvt(b4[q], hi, lo);
                Bh[(lc4 * 4 + q) * SAPAD + m] = hi;
                Bl[(lc4 * 4 + q) * SAPAD + m] = lo;
            }
        }
        __syncthreads();

#pragma unroll
        for (int ks = 0; ks < 4; ks++) {
            int kb = ks * 8;
            uint32_t ah[4][4], al[4][4];
#pragma unroll
            for (int mt = 0; mt < 4; mt++) {
                int m0 = wm * 64 + mt * 16 + gID;
                ah[mt][0] = __float_as_uint(Ah[(kb + tig    ) * SAPAD + m0    ]);
                ah[mt][1] = __float_as_uint(Ah[(kb + tig    ) * SAPAD + m0 + 8]);
                ah[mt][2] = __float_as_uint(Ah[(kb + tig + 4) * SAPAD + m0    ]);
                ah[mt][3] = __float_as_uint(Ah[(kb + tig + 4) * SAPAD + m0 + 8]);
                al[mt][0] = __float_as_uint(Al[(kb + tig    ) * SAPAD + m0    ]);
                al[mt][1] = __float_as_uint(Al[(kb + tig    ) * SAPAD + m0 + 8]);
                al[mt][2] = __float_as_uint(Al[(kb + tig + 4) * SAPAD + m0    ]);
                al[mt][3] = __float_as_uint(Al[(kb + tig + 4) * SAPAD + m0 + 8]);
            }
#pragma unroll
            for (int nt = 0; nt < 4; nt++) {
                int n0 = wn * 32 + nt * 8 + gID;
                uint32_t bh0 = __float_as_uint(Bh[(kb + tig    ) * SAPAD + n0]);
                uint32_t bh1 = __float_as_uint(Bh[(kb + tig + 4) * SAPAD + n0]);
                uint32_t bl0 = __float_as_uint(Bl[(kb + tig    ) * SAPAD + n0]);
                uint32_t bl1 = __float_as_uint(Bl[(kb + tig + 4) * SAPAD + n0]);
#pragma unroll
                for (int mt = 0; mt < 4; mt++) {
                    mma_tf32(acc[mt][nt], ah[mt][0], ah[mt][1], ah[mt][2], ah[mt][3], bh0, bh1);
                    mma_tf32(acc[mt][nt], al[mt][0], al[mt][1], al[mt][2], al[mt][3], bh0, bh1);
                    mma_tf32(acc[mt][nt], ah[mt][0], ah[mt][1], ah[mt][2], ah[mt][3], bl0, bl1);
                }
            }
        }
        __syncthreads();
    }

#pragma unroll
    for (int mt = 0; mt < 4; mt++) {
#pragma unroll
        for (int nt = 0; nt < 4; nt++) {
            int r0 = rowBase + wm * 64 + mt * 16 + gID;
            int c0 = colBase + wn * 32 + nt * 8 + tig * 2;
            float bi0 = bias ? bias[c0] : 0.f;
            float bi1 = bias ? bias[c0 + 1] : 0.f;
            float* p0 = C + (size_t)r0 * N + c0;
            float* p1 = C + (size_t)(r0 + 8) * N + c0;
            *(float2*)p0 = make_float2(acc[mt][nt][0] + bi0, acc[mt][nt][1] + bi1);
            *(float2*)p1 = make_float2(acc[mt][nt][2] + bi0, acc[mt][nt][3] + bi1);
        }
    }
}

// =====================================================================
// Persistent RNN recurrence, COALESCED transposed hidden state.
// hT layout: [2][HID][BATCH] — h element (b, k) at hT[buf][k*32 + b].
// Block owns 8 output cols; warp w owns k-slice [w*128, (w+1)*128).
// lane = batch. h loads: LDG.32 coalesced (nL=1), L2-scope (__ldcg).
// W slice in smem transposed swT[k][8] -> 2 broadcast LDS.128 per k.
// =====================================================================
__device__ __forceinline__ void st_release_int(int* p, int v)
{
    asm volatile("st.release.gpu.global.s32 [%0], %1;" :: "l"(p), "r"(v) : "memory");
}
__device__ __forceinline__ int ld_acquire_int(const int* p)
{
    int v;
    asm volatile("ld.acquire.gpu.global.s32 %0, [%1];" : "=r"(v) : "l"(p) : "memory");
    return v;
}

__global__ void reset_flags_k()
{
    g_flags[threadIdx.x] = 0;
}

// transpose hidden[l] [B][H] -> g_ht buf0 [H][B]
__global__ __launch_bounds__(256)
void htrans_in_k(const float* __restrict__ hsrc)
{
    int idx = blockIdx.x * 256 + threadIdx.x;   // over 32768
    int h = idx >> 5;
    int b = idx & 31;
    g_ht[(size_t)h * BATCH + b] = hsrc[(size_t)b * HID + h];
}

__global__ __launch_bounds__(256)
void rnn_persist(const float* __restrict__ xw,   // [128][32][1024]
                 const float* __restrict__ Whh,  // [1024][1024]
                 const float* __restrict__ bhh,  // [1024]
                 float* __restrict__ yseq)       // [128][32][1024]
{
    __shared__ float swT[HID][8];       // 32 KB: swT[k][j] = Whh[jbase+j][k]
    __shared__ float sb[8];
    __shared__ float red[8][BATCH][8];  // 8 KB partials

    int tid = threadIdx.x;
    int bid = blockIdx.x;
    int jbase = bid * 8;

    // load W slice transposed (coalesced gmem reads)
    for (int idx = tid; idx < 8 * HID; idx += 256) {
        int j = idx >> 10;          // 0..7
        int k = idx & 1023;
        swT[k][j] = Whh[(size_t)(jbase + j) * HID + k];
    }
    if (tid < 8) sb[tid] = bhh[jbase + tid];
    __syncthreads();

    int w    = tid >> 5;     // warp 0..7 -> k-slice
    int lane = tid & 31;     // lane -> batch row
    int kbase = w * 128;
    int rb = tid >> 3;       // reduce mapping: batch
    int rj = tid & 7;        // reduce mapping: local j

#pragma unroll 1
    for (int t = 0; t < T_LEN; t++) {
        const float* hcur = g_ht + (size_t)(t & 1) * HID * BATCH;
        float*       hnxt = g_ht + (size_t)((t + 1) & 1) * HID * BATCH;

        float acc[8];
#pragma unroll
        for (int j = 0; j < 8; j++) acc[j] = 0.f;

#pragma unroll 1
        for (int kk = 0; kk < 128; kk += 8) {
            float hv[8];
#pragma unroll
            for (int u = 0; u < 8; u++)
                hv[u] = __ldcg(hcur + (size_t)(kbase + kk + u) * BATCH + lane);
#pragma unroll
            for (int u = 0; u < 8; u++) {
                float4 wa = *(const float4*)&swT[kbase + kk + u][0];
                float4 wb = *(const float4*)&swT[kbase + kk + u][4];
                acc[0] += wa.x * hv[u];
                acc[1] += wa.y * hv[u];
                acc[2] += wa.z * hv[u];
                acc[3] += wa.w * hv[u];
                acc[4] += wb.x * hv[u];
                acc[5] += wb.y * hv[u];
                acc[6] += wb.z * hv[u];
                acc[7] += wb.w * hv[u];
            }
        }

        // cross-warp (k-slice) reduction
        *(float4*)&red[w][lane][0] = make_float4(acc[0], acc[1], acc[2], acc[3]);
        *(float4*)&red[w][lane][4] = make_float4(acc[4], acc[5], acc[6], acc[7]);
        __syncthreads();
        {
            float s = 0.f;
#pragma unroll
            for (int ww = 0; ww < 8; ww++) s += red[ww][rb][rj];
            float pre = s + sb[rj] + xw[(size_t)t * BATCH * HID + (size_t)rb * HID + jbase + rj];
            float v = tanhf(pre);
            __stcg(hnxt + (size_t)(jbase + rj) * BATCH + rb, v);
            yseq[(size_t)t * BATCH * HID + (size_t)rb * HID + jbase + rj] = v;
        }

        // grid barrier
        __threadfence();
        __syncthreads();
        if (tid == 0) st_release_int(&g_flags[bid], t + 1);
        if (tid < 128) {
            while (ld_acquire_int(&g_flags[tid]) < t + 1) { }
        }
        __syncthreads();
    }
}

// =====================================================================
// In-place log_softmax over rows of 32000. Row cached in 128 KB smem.
// =====================================================================
__global__ __launch_bounds__(256)
void logsoftmax_k(float* __restrict__ out)
{
    extern __shared__ float srow[];
    __shared__ float red[256];
    int tid = threadIdx.x;
    float4* p4 = (float4*)(out + (size_t)blockIdx.x * VOCAB);

    float m = -3.4e38f;
#pragma unroll 4
    for (int i = tid; i < VOCAB / 4; i += 256) {
        float4 v = p4[i];
        *(float4*)&srow[i * 4] = v;
        m = fmaxf(m, fmaxf(fmaxf(v.x, v.y), fmaxf(v.z, v.w)));
    }
    red[tid] = m; __syncthreads();
    for (int s = 128; s > 0; s >>= 1) {
        if (tid < s) red[tid] = fmaxf(red[tid], red[tid + s]);
        __syncthreads();
    }
    float rm = red[0]; __syncthreads();

    float sum = 0.f;
    for (int i = tid; i < VOCAB; i += 256) sum += expf(srow[i] - rm);
    red[tid] = sum; __syncthreads();
    for (int s = 128; s > 0; s >>= 1) {
        if (tid < s) red[tid] += red[tid + s];
        __syncthreads();
    }
    float lz = rm + logf(red[0]);

    for (int i = tid; i < VOCAB / 4; i += 256) {
        float4 v = *(float4*)&srow[i * 4];
        v.x -= lz; v.y -= lz; v.z -= lz; v.w -= lz;
        p4[i] = v;
    }
}

// =====================================================================
// host orchestration (graph-capturable)
// =====================================================================
extern "C" void kernel_launch(void* const* d_in, const int* in_sizes, int n_in,
                              void* d_out, int out_size)
{
    const int*   input_x = (const int*)  d_in[0];
    const float* hidden  = (const float*)d_in[1];
    const float* emb     = (const float*)d_in[2];
    const float* W_ih    = (const float*)d_in[3];
    const float* W_hh    = (const float*)d_in[4];
    const float* b_ih    = (const float*)d_in[5];
    const float* b_hh    = (const float*)d_in[6];
    const float* W_out   = (const float*)d_in[7];
    const float* b_out   = (const float*)d_in[8];
    float* out = (float*)d_out;

    float *gx, *gxw;
    cudaGetSymbolAddress((void**)&gx,  g_x);
    cudaGetSymbolAddress((void**)&gxw, g_xw);

    cudaFuncSetAttribute(logsoftmax_k,
                         cudaFuncAttributeMaxDynamicSharedMemorySize,
                         VOCAB * (int)sizeof(float));
    cudaFuncSetAttribute(gemm_split3,
                         cudaFuncAttributeMaxDynamicSharedMemorySize,
                         4 * BK * SAPAD * (int)sizeof(float));

    const int writeHidden = (size_t)out_size >= LOGITS_ELEMS + HIDDEN_ELEMS;

    // 1) embedding gather
    embed_k<<<MROWS, 256>>>(input_x, emb, gx);

    for (int l = 0; l < 2; l++) {
        const float* Wi = W_ih + (size_t)l * HID * HID;
        const float* Wh = W_hh + (size_t)l * HID * HID;
        const float* bi = b_ih + (size_t)l * HID;
        const float* bh = b_hh + (size_t)l * HID;

        // init transposed hidden (buf 0)
        htrans_in_k<<<BATCH * HID / 256, 256>>>(hidden + (size_t)l * BATCH * HID);

        // input projection: fused 3-term tf32 split, single launch
        dim3 gp(MROWS / BM, HID / BN);
        gemm_split3<<<gp, 256, 4 * BK * SAPAD * (int)sizeof(float)>>>(
            gx, Wi, gxw, bi, MROWS, HID, HID);

        // persistent recurrence (exact fp32)
        reset_flags_k<<<1, 128>>>();
        rnn_persist<<<128, 256>>>(gxw, Wh, bh, gx);

        // new_hidden[l] = y[T-1]
        if (writeHidden)
            cudaMemcpyAsync(out + LOGITS_ELEMS + (size_t)l * BATCH * HID,
                            gx + (size_t)(T_LEN - 1) * BATCH * HID,
                            (size_t)BATCH * HID * sizeof(float),
                            cudaMemcpyDeviceToDevice, 0);
    }

    // output projection (single-pass tf32, no downstream accumulation)
    dim3 go(MROWS / BM, VOCAB / BN);
    gemm_tf32<<<go, 256>>>(gx, W_out, out, b_out, MROWS, VOCAB, HID);

    // in-place log_softmax
    logsoftmax_k<<<MROWS, 256, VOCAB * (int)sizeof(float)>>>(out);
}

// round 9
// speedup vs baseline: 1.5192x; 1.5192x over previous
#include <cuda_runtime.h>
#include <cuda_bf16.h>
#include <cstdint>
#include <cstddef>

// ---------------- problem constants ----------------
#define T_LEN 128
#define BATCH 32
#define HID   1024
#define VOCAB 32000
#define MROWS (T_LEN * BATCH)        // 4096
#define LOGITS_ELEMS ((size_t)MROWS * VOCAB)   // 131072000
#define HIDDEN_ELEMS (2 * BATCH * HID)         // 65536

// ---------------- device scratch (no runtime alloc allowed) ----------------
__device__ float g_x [MROWS * HID];     // layer input / output sequence (16 MB)
__device__ float g_xw[MROWS * HID];     // precomputed input projection  (16 MB)
// hidden ping-pong, float4-quad layout: buf[q*BATCH + b] holds h[4q..4q+3][b]
__device__ float4 g_h4[2 * (HID / 4) * BATCH];
__device__ int   g_ctr;                 // persistent-kernel barrier counter

// =====================================================================
// Embedding gather
// =====================================================================
__global__ __launch_bounds__(256)
void embed_k(const int* __restrict__ idx, const float* __restrict__ emb,
             float* __restrict__ xout)
{
    int row = blockIdx.x;
    int tok = idx[row];
    const float4* s = (const float4*)(emb + (size_t)tok * HID);
    float4* d = (float4*)(xout + (size_t)row * HID);
    d[threadIdx.x] = s[threadIdx.x];
}

// =====================================================================
// tf32 helpers
// =====================================================================
__device__ __forceinline__ float tf32_hi(float v)
{
    uint32_t t;
    asm("cvt.rna.tf32.f32 %0, %1;" : "=r"(t) : "f"(v));
    return __uint_as_float(t);
}
__device__ __forceinline__ void split_cvt(float v, float& hi, float& lo)
{
    hi = tf32_hi(v);
    lo = tf32_hi(v - hi);
}

__device__ __forceinline__ void mma_tf32(float c[4], uint32_t a0, uint32_t a1,
                                         uint32_t a2, uint32_t a3,
                                         uint32_t b0, uint32_t b1)
{
    asm volatile(
        "mma.sync.aligned.m16n8k8.row.col.f32.tf32.tf32.f32 "
        "{%0,%1,%2,%3}, {%4,%5,%6,%7}, {%8,%9}, {%0,%1,%2,%3};"
        : "+f"(c[0]), "+f"(c[1]), "+f"(c[2]), "+f"(c[3])
        : "r"(a0), "r"(a1), "r"(a2), "r"(a3), "r"(b0), "r"(b1));
}

#define BM 128
#define BN 128
#define BK 32
#define SAPAD 132

// =====================================================================
// Single-pass tf32 GEMM (output projection): C = A[M,K] * B[N,K]^T + bias
// =====================================================================
__global__ __launch_bounds__(256)
void gemm_tf32(const float* __restrict__ A, const float* __restrict__ B,
               float* __restrict__ C, const float* __restrict__ bias,
               int M, int N, int K)
{
    __shared__ float As[BK][SAPAD];
    __shared__ float Bs[BK][SAPAD];

    int tid  = threadIdx.x;
    int warp = tid >> 5, lane = tid & 31;
    int wm   = warp >> 2;
    int wn   = warp & 3;
    int gID  = lane >> 2;
    int tig  = lane & 3;

    int rowBase = blockIdx.x * BM;
    int colBase = blockIdx.y * BN;

    int lc4 = tid & 7;
    int lr  = tid >> 3;
    const float* Aload = A + (size_t)(rowBase + lr) * K + lc4 * 4;
    const float* Bload = B + (size_t)(colBase + lr) * K + lc4 * 4;

    float4 aReg[4], bReg[4];

    float acc[4][4][4];
#pragma unroll
    for (int mt = 0; mt < 4; mt++)
#pragma unroll
        for (int nt = 0; nt < 4; nt++)
#pragma unroll
            for (int q = 0; q < 4; q++) acc[mt][nt][q] = 0.f;

    const int NT = K / BK;

#pragma unroll
    for (int i = 0; i < 4; i++) {
        aReg[i] = *(const float4*)(Aload + (size_t)i * 32 * K);
        bReg[i] = *(const float4*)(Bload + (size_t)i * 32 * K);
    }
#pragma unroll
    for (int i = 0; i < 4; i++) {
        int m = lr + i * 32;
        float va[4] = {aReg[i].x, aReg[i].y, aReg[i].z, aReg[i].w};
        float vb[4] = {bReg[i].x, bReg[i].y, bReg[i].z, bReg[i].w};
#pragma unroll
        for (int q = 0; q < 4; q++) {
            As[lc4 * 4 + q][m] = tf32_hi(va[q]);
            Bs[lc4 * 4 + q][m] = tf32_hi(vb[q]);
        }
    }
    __syncthreads();

    for (int kt = 0; kt < NT; kt++) {
        if (kt + 1 < NT) {
            const float* ap = Aload + (size_t)(kt + 1) * BK;
            const float* bp = Bload + (size_t)(kt + 1) * BK;
#pragma unroll
            for (int i = 0; i < 4; i++) {
                aReg[i] = *(const float4*)(ap + (size_t)i * 32 * K);
                bReg[i] = *(const float4*)(bp + (size_t)i * 32 * K);
            }
        }
#pragma unroll
        for (int ks = 0; ks < 4; ks++) {
            int kb = ks * 8;
            uint32_t af[4][4];
#pragma unroll
            for (int mt = 0; mt < 4; mt++) {
                int m0 = wm * 64 + mt * 16 + gID;
                af[mt][0] = __float_as_uint(As[kb + tig    ][m0    ]);
                af[mt][1] = __float_as_uint(As[kb + tig    ][m0 + 8]);
                af[mt][2] = __float_as_uint(As[kb + tig + 4][m0    ]);
                af[mt][3] = __float_as_uint(As[kb + tig + 4][m0 + 8]);
            }
#pragma unroll
            for (int nt = 0; nt < 4; nt++) {
                int n0 = wn * 32 + nt * 8 + gID;
                uint32_t b0 = __float_as_uint(Bs[kb + tig    ][n0]);
                uint32_t b1 = __float_as_uint(Bs[kb + tig + 4][n0]);
#pragma unroll
                for (int mt = 0; mt < 4; mt++)
                    mma_tf32(acc[mt][nt], af[mt][0], af[mt][1], af[mt][2],
                             af[mt][3], b0, b1);
            }
        }
        __syncthreads();
        if (kt + 1 < NT) {
#pragma unroll
            for (int i = 0; i < 4; i++) {
                int m = lr + i * 32;
                float va[4] = {aReg[i].x, aReg[i].y, aReg[i].z, aReg[i].w};
                float vb[4] = {bReg[i].x, bReg[i].y, bReg[i].z, bReg[i].w};
#pragma unroll
                for (int q = 0; q < 4; q++) {
                    As[lc4 * 4 + q][m] = tf32_hi(va[q]);
                    Bs[lc4 * 4 + q][m] = tf32_hi(vb[q]);
                }
            }
            __syncthreads();
        }
    }

#pragma unroll
    for (int mt = 0; mt < 4; mt++) {
#pragma unroll
        for (int nt = 0; nt < 4; nt++) {
            int r0 = rowBase + wm * 64 + mt * 16 + gID;
            int c0 = colBase + wn * 32 + nt * 8 + tig * 2;
            float bi0 = bias ? bias[c0] : 0.f;
            float bi1 = bias ? bias[c0 + 1] : 0.f;
            float* p0 = C + (size_t)r0 * N + c0;
            float* p1 = C + (size_t)(r0 + 8) * N + c0;
            *(float2*)p0 = make_float2(acc[mt][nt][0] + bi0, acc[mt][nt][1] + bi1);
            *(float2*)p1 = make_float2(acc[mt][nt][2] + bi0, acc[mt][nt][3] + bi1);
        }
    }
}

// =====================================================================
// Fused 3-term tf32 split GEMM (near-fp32): C = A*B^T + bias in ONE pass.
// =====================================================================
__global__ __launch_bounds__(256)
void gemm_split3(const float* __restrict__ A, const float* __restrict__ B,
                 float* __restrict__ C, const float* __restrict__ bias,
                 int M, int N, int K)
{
    extern __shared__ float smem[];
    float* Ah = smem;
    float* Al = smem + BK * SAPAD;
    float* Bh = smem + 2 * BK * SAPAD;
    float* Bl = smem + 3 * BK * SAPAD;

    int tid  = threadIdx.x;
    int warp = tid >> 5, lane = tid & 31;
    int wm   = warp >> 2;
    int wn   = warp & 3;
    int gID  = lane >> 2;
    int tig  = lane & 3;

    int rowBase = blockIdx.x * BM;
    int colBase = blockIdx.y * BN;

    int lc4 = tid & 7;
    int lr  = tid >> 3;
    const float* Aload = A + (size_t)(rowBase + lr) * K + lc4 * 4;
    const float* Bload = B + (size_t)(colBase + lr) * K + lc4 * 4;

    float acc[4][4][4];
#pragma unroll
    for (int mt = 0; mt < 4; mt++)
#pragma unroll
        for (int nt = 0; nt < 4; nt++)
#pragma unroll
            for (int q = 0; q < 4; q++) acc[mt][nt][q] = 0.f;

    const int NT = K / BK;

    for (int kt = 0; kt < NT; kt++) {
#pragma unroll
        for (int i = 0; i < 4; i++) {
            float4 va = *(const float4*)(Aload + (size_t)kt * BK + (size_t)i * 32 * K);
            float4 vb = *(const float4*)(Bload + (size_t)kt * BK + (size_t)i * 32 * K);
            int m = lr + i * 32;
            float a4[4] = {va.x, va.y, va.z, va.w};
            float b4[4] = {vb.x, vb.y, vb.z, vb.w};
#pragma unroll
            for (int q = 0; q < 4; q++) {
                float hi, lo;
                split_cvt(a4[q], hi, lo);
                Ah[(lc4 * 4 + q) * SAPAD + m] = hi;
                Al[(lc4 * 4 + q) * SAPAD + m] = lo;
                split_cvt(b4[q], hi, lo);
                Bh[(lc4 * 4 + q) * SAPAD + m] = hi;
                Bl[(lc4 * 4 + q) * SAPAD + m] = lo;
            }
        }
        __syncthreads();

#pragma unroll
        for (int ks = 0; ks < 4; ks++) {
            int kb = ks * 8;
            uint32_t ah[4][4], al[4][4];
#pragma unroll
            for (int mt = 0; mt < 4; mt++) {
                int m0 = wm * 64 + mt * 16 + gID;
                ah[mt][0] = __float_as_uint(Ah[(kb + tig    ) * SAPAD + m0    ]);
                ah[mt][1] = __float_as_uint(Ah[(kb + tig    ) * SAPAD + m0 + 8]);
                ah[mt][2] = __float_as_uint(Ah[(kb + tig + 4) * SAPAD + m0    ]);
                ah[mt][3] = __float_as_uint(Ah[(kb + tig + 4) * SAPAD + m0 + 8]);
                al[mt][0] = __float_as_uint(Al[(kb + tig    ) * SAPAD + m0    ]);
                al[mt][1] = __float_as_uint(Al[(kb + tig    ) * SAPAD + m0 + 8]);
                al[mt][2] = __float_as_uint(Al[(kb + tig + 4) * SAPAD + m0    ]);
                al[mt][3] = __float_as_uint(Al[(kb + tig + 4) * SAPAD + m0 + 8]);
            }
#pragma unroll
            for (int nt = 0; nt < 4; nt++) {
                int n0 = wn * 32 + nt * 8 + gID;
                uint32_t bh0 = __float_as_uint(Bh[(kb + tig    ) * SAPAD + n0]);
                uint32_t bh1 = __float_as_uint(Bh[(kb + tig + 4) * SAPAD + n0]);
                uint32_t bl0 = __float_as_uint(Bl[(kb + tig    ) * SAPAD + n0]);
                uint32_t bl1 = __float_as_uint(Bl[(kb + tig + 4) * SAPAD + n0]);
#pragma unroll
                for (int mt = 0; mt < 4; mt++) {
                    mma_tf32(acc[mt][nt], ah[mt][0], ah[mt][1], ah[mt][2], ah[mt][3], bh0, bh1);
                    mma_tf32(acc[mt][nt], al[mt][0], al[mt][1], al[mt][2], al[mt][3], bh0, bh1);
                    mma_tf32(acc[mt][nt], ah[mt][0], ah[mt][1], ah[mt][2], ah[mt][3], bl0, bl1);
                }
            }
        }
        __syncthreads();
    }

#pragma unroll
    for (int mt = 0; mt < 4; mt++) {
#pragma unroll
        for (int nt = 0; nt < 4; nt++) {
            int r0 = rowBase + wm * 64 + mt * 16 + gID;
            int c0 = colBase + wn * 32 + nt * 8 + tig * 2;
            float bi0 = bias ? bias[c0] : 0.f;
            float bi1 = bias ? bias[c0 + 1] : 0.f;
            float* p0 = C + (size_t)r0 * N + c0;
            float* p1 = C + (size_t)(r0 + 8) * N + c0;
            *(float2*)p0 = make_float2(acc[mt][nt][0] + bi0, acc[mt][nt][1] + bi1);
            *(float2*)p1 = make_float2(acc[mt][nt][2] + bi0, acc[mt][nt][3] + bi1);
        }
    }
}

// =====================================================================
// Persistent RNN recurrence v3 (first real measurement of this design).
//  - cg-style centralized counter barrier (release atomic + acquire poll),
//    NO per-thread threadfence; only tid0 polls, with nanosleep backoff.
//  - h ping-pong in float4-quad layout [HID/4][BATCH]: 32 coalesced
//    LDG.128 per thread, software-pipelined 2-deep.
//  - counter reset piggybacked on htrans_in_k (no reset launch).
// =====================================================================
__device__ __forceinline__ void red_add_release_gpu(int* p, int v)
{
    asm volatile("red.release.gpu.global.add.s32 [%0], %1;" :: "l"(p), "r"(v) : "memory");
}
__device__ __forceinline__ int ld_acquire_int(const int* p)
{
    int v;
    asm volatile("ld.acquire.gpu.global.s32 %0, [%1];" : "=r"(v) : "l"(p) : "memory");
    return v;
}

// transpose hidden[l] [B][H] -> g_h4 buf0 quad layout; reset barrier counter
__global__ __launch_bounds__(256)
void htrans_in_k(const float* __restrict__ hsrc)
{
    if (blockIdx.x == 0 && threadIdx.x == 0) g_ctr = 0;
    int idx = blockIdx.x * 256 + threadIdx.x;   // over 8192 quads
    int q = idx >> 5;          // 0..255  (k-quad)
    int b = idx & 31;
    float4 v = make_float4(hsrc[(size_t)b * HID + q * 4 + 0],
                           hsrc[(size_t)b * HID + q * 4 + 1],
                           hsrc[(size_t)b * HID + q * 4 + 2],
                           hsrc[(size_t)b * HID + q * 4 + 3]);
    g_h4[(size_t)q * BATCH + b] = v;
}

__global__ __launch_bounds__(256)
void rnn_persist(const float* __restrict__ xw,   // [128][32][1024]
                 const float* __restrict__ Whh,  // [1024][1024]
                 const float* __restrict__ bhh,  // [1024]
                 float* __restrict__ yseq)       // [128][32][1024]
{
    __shared__ float swT[HID][8];       // 32 KB: swT[k][j] = Whh[jbase+j][k]
    __shared__ float sb[8];
    __shared__ float red[8][BATCH][8];  // 8 KB partials

    int tid = threadIdx.x;
    int bid = blockIdx.x;
    int jbase = bid * 8;

    // load W slice transposed (coalesced gmem reads)
    for (int idx = tid; idx < 8 * HID; idx += 256) {
        int j = idx >> 10;
        int k = idx & 1023;
        swT[k][j] = Whh[(size_t)(jbase + j) * HID + k];
    }
    if (tid < 8) sb[tid] = bhh[jbase + tid];
    __syncthreads();

    int w    = tid >> 5;        // warp -> k slice
    int lane = tid & 31;        // lane -> batch
    int kqbase = w * 32;        // 32 quads (=128 k) per warp
    int rb = tid >> 3;          // reduce: batch
    int rj = tid & 7;           // reduce: local j
    int jout = jbase + rj;
    int houtOff = ((jout >> 2) * BATCH + rb) * 4 + (jout & 3);

#pragma unroll 1
    for (int t = 0; t < T_LEN; t++) {
        const float4* hcur = g_h4 + (size_t)(t & 1) * (HID / 4) * BATCH;
        float*        hnxt = (float*)(g_h4 + (size_t)((t + 1) & 1) * (HID / 4) * BATCH);

        float xval = xw[(size_t)t * BATCH * HID + (size_t)rb * HID + jout];

        float acc[8];
#pragma unroll
        for (int j = 0; j < 8; j++) acc[j] = 0.f;

        float4 hv[8], hp[8];
#pragma unroll
        for (int i = 0; i < 8; i++)
            hv[i] = __ldcg(hcur + (size_t)(kqbase + i) * BATCH + lane);

#pragma unroll
        for (int c = 0; c < 4; c++) {
            if (c < 3) {
#pragma unroll
                for (int i = 0; i < 8; i++)
                    hp[i] = __ldcg(hcur + (size_t)(kqbase + (c + 1) * 8 + i) * BATCH + lane);
            }
#pragma unroll
            for (int i = 0; i < 8; i++) {
                int k0 = (kqbase + c * 8 + i) * 4;
                float hd[4] = {hv[i].x, hv[i].y, hv[i].z, hv[i].w};
#pragma unroll
                for (int d = 0; d < 4; d++) {
                    float4 wa = *(const float4*)&swT[k0 + d][0];
                    float4 wb = *(const float4*)&swT[k0 + d][4];
                    acc[0] += wa.x * hd[d];
                    acc[1] += wa.y * hd[d];
                    acc[2] += wa.z * hd[d];
                    acc[3] += wa.w * hd[d];
                    acc[4] += wb.x * hd[d];
                    acc[5] += wb.y * hd[d];
                    acc[6] += wb.z * hd[d];
                    acc[7] += wb.w * hd[d];
                }
            }
            if (c < 3) {
#pragma unroll
                for (int i = 0; i < 8; i++) hv[i] = hp[i];
            }
        }

        // cross-warp (k-slice) reduction
        *(float4*)&red[w][lane][0] = make_float4(acc[0], acc[1], acc[2], acc[3]);
        *(float4*)&red[w][lane][4] = make_float4(acc[4], acc[5], acc[6], acc[7]);
        __syncthreads();
        {
            float s = 0.f;
#pragma unroll
            for (int ww = 0; ww < 8; ww++) s += red[ww][rb][rj];
            float v = tanhf(s + sb[rj] + xval);
            __stcg(hnxt + houtOff, v);
            yseq[(size_t)t * BATCH * HID + (size_t)rb * HID + jout] = v;
        }

        // grid barrier (cooperative-groups pattern: no per-thread fence,
        // single release-add + single acquire poller with HW-sleep backoff)
        __syncthreads();
        if (tid == 0) {
            red_add_release_gpu(&g_ctr, 1);
            int target = 128 * (t + 1);
            while (ld_acquire_int(&g_ctr) < target) {
                __nanosleep(64);
            }
        }
        __syncthreads();
    }
}

// =====================================================================
// In-place log_softmax over rows of 32000. Row cached in 128 KB smem.
// =====================================================================
__global__ __launch_bounds__(256)
void logsoftmax_k(float* __restrict__ out)
{
    extern __shared__ float srow[];
    __shared__ float red[256];
    int tid = threadIdx.x;
    float4* p4 = (float4*)(out + (size_t)blockIdx.x * VOCAB);

    float m = -3.4e38f;
#pragma unroll 4
    for (int i = tid; i < VOCAB / 4; i += 256) {
        float4 v = p4[i];
        *(float4*)&srow[i * 4] = v;
        m = fmaxf(m, fmaxf(fmaxf(v.x, v.y), fmaxf(v.z, v.w)));
    }
    red[tid] = m; __syncthreads();
    for (int s = 128; s > 0; s >>= 1) {
        if (tid < s) red[tid] = fmaxf(red[tid], red[tid + s]);
        __syncthreads();
    }
    float rm = red[0]; __syncthreads();

    float sum = 0.f;
    for (int i = tid; i < VOCAB; i += 256) sum += expf(srow[i] - rm);
    red[tid] = sum; __syncthreads();
    for (int s = 128; s > 0; s >>= 1) {
        if (tid < s) red[tid] += red[tid + s];
        __syncthreads();
    }
    float lz = rm + logf(red[0]);

    for (int i = tid; i < VOCAB / 4; i += 256) {
        float4 v = *(float4*)&srow[i * 4];
        v.x -= lz; v.y -= lz; v.z -= lz; v.w -= lz;
        p4[i] = v;
    }
}

// =====================================================================
// host orchestration (graph-capturable)
// =====================================================================
extern "C" void kernel_launch(void* const* d_in, const int* in_sizes, int n_in,
                              void* d_out, int out_size)
{
    const int*   input_x = (const int*)  d_in[0];
    const float* hidden  = (const float*)d_in[1];
    const float* emb     = (const float*)d_in[2];
    const float* W_ih    = (const float*)d_in[3];
    const float* W_hh    = (const float*)d_in[4];
    const float* b_ih    = (const float*)d_in[5];
    const float* b_hh    = (const float*)d_in[6];
    const float* W_out   = (const float*)d_in[7];
    const float* b_out   = (const float*)d_in[8];
    float* out = (float*)d_out;

    float *gx, *gxw;
    cudaGetSymbolAddress((void**)&gx,  g_x);
    cudaGetSymbolAddress((void**)&gxw, g_xw);

    cudaFuncSetAttribute(logsoftmax_k,
                         cudaFuncAttributeMaxDynamicSharedMemorySize,
                         VOCAB * (int)sizeof(float));
    cudaFuncSetAttribute(gemm_split3,
                         cudaFuncAttributeMaxDynamicSharedMemorySize,
                         4 * BK * SAPAD * (int)sizeof(float));

    const int writeHidden = (size_t)out_size >= LOGITS_ELEMS + HIDDEN_ELEMS;

    // 1) embedding gather
    embed_k<<<MROWS, 256>>>(input_x, emb, gx);

    for (int l = 0; l < 2; l++) {
        const float* Wi = W_ih + (size_t)l * HID * HID;
        const float* Wh = W_hh + (size_t)l * HID * HID;
        const float* bi = b_ih + (size_t)l * HID;
        const float* bh = b_hh + (size_t)l * HID;

        // init transposed hidden (buf 0) + reset barrier counter
        htrans_in_k<<<BATCH * HID / 256, 256>>>(hidden + (size_t)l * BATCH * HID);

        // input projection: fused 3-term tf32 split, single launch
        dim3 gp(MROWS / BM, HID / BN);
        gemm_split3<<<gp, 256, 4 * BK * SAPAD * (int)sizeof(float)>>>(
            gx, Wi, gxw, bi, MROWS, HID, HID);

        // persistent recurrence (exact fp32)
        rnn_persist<<<128, 256>>>(gxw, Wh, bh, gx);

        // new_hidden[l] = y[T-1]
        if (writeHidden)
            cudaMemcpyAsync(out + LOGITS_ELEMS + (size_t)l * BATCH * HID,
                            gx + (size_t)(T_LEN - 1) * BATCH * HID,
                            (size_t)BATCH * HID * sizeof(float),
                            cudaMemcpyDeviceToDevice, 0);
    }

    // output projection (single-pass tf32, no downstream accumulation)
    dim3 go(MROWS / BM, VOCAB / BN);
    gemm_tf32<<<go, 256>>>(gx, W_out, out, b_out, MROWS, VOCAB, HID);

    // in-place log_softmax
    logsoftmax_k<<<MROWS, 256, VOCAB * (int)sizeof(float)>>>(out);
}

// round 10
// speedup vs baseline: 1.7591x; 1.1579x over previous
#include <cuda_runtime.h>
#include <cuda_bf16.h>
#include <cstdint>
#include <cstddef>

// ---------------- problem constants ----------------
#define T_LEN 128
#define BATCH 32
#define HID   1024
#define VOCAB 32000
#define MROWS (T_LEN * BATCH)        // 4096
#define LOGITS_ELEMS ((size_t)MROWS * VOCAB)   // 131072000
#define HIDDEN_ELEMS (2 * BATCH * HID)         // 65536

// ---------------- device scratch (no runtime alloc allowed) ----------------
__device__ float g_x [MROWS * HID];     // layer input / output sequence (16 MB)
__device__ float g_xw[MROWS * HID];     // precomputed input projection  (16 MB)
// hidden ping-pong, float4-quad layout: buf[q*BATCH + b] holds h[4q..4q+3][b]
__device__ float4 g_h4[2 * (HID / 4) * BATCH];
__device__ int   g_ctr;                 // persistent-kernel barrier counter

// =====================================================================
// Embedding gather
// =====================================================================
__global__ __launch_bounds__(256)
void embed_k(const int* __restrict__ idx, const float* __restrict__ emb,
             float* __restrict__ xout)
{
    int row = blockIdx.x;
    int tok = idx[row];
    const float4* s = (const float4*)(emb + (size_t)tok * HID);
    float4* d = (float4*)(xout + (size_t)row * HID);
    d[threadIdx.x] = s[threadIdx.x];
}

// =====================================================================
// tf32 helpers
// =====================================================================
__device__ __forceinline__ float tf32_hi(float v)
{
    uint32_t t;
    asm("cvt.rna.tf32.f32 %0, %1;" : "=r"(t) : "f"(v));
    return __uint_as_float(t);
}
__device__ __forceinline__ void split_cvt(float v, float& hi, float& lo)
{
    hi = tf32_hi(v);
    lo = tf32_hi(v - hi);
}

__device__ __forceinline__ void mma_tf32(float c[4], uint32_t a0, uint32_t a1,
                                         uint32_t a2, uint32_t a3,
                                         uint32_t b0, uint32_t b1)
{
    asm volatile(
        "mma.sync.aligned.m16n8k8.row.col.f32.tf32.tf32.f32 "
        "{%0,%1,%2,%3}, {%4,%5,%6,%7}, {%8,%9}, {%0,%1,%2,%3};"
        : "+f"(c[0]), "+f"(c[1]), "+f"(c[2]), "+f"(c[3])
        : "r"(a0), "r"(a1), "r"(a2), "r"(a3), "r"(b0), "r"(b1));
}

__device__ __forceinline__ void cp16(uint32_t dst, const void* src)
{
    asm volatile("cp.async.cg.shared.global [%0], [%1], 16;" :: "r"(dst), "l"(src));
}

#define BM 128
#define BN 128
#define BK 32
#define SAPAD 132

// =====================================================================
// Output projection GEMM: C = A[M,K] * B[N,K]^T + bias.
// cp.async double-buffered, raw f32 operands (HMMA.tf32 truncates in HW).
// Smem tiles [row][36] (conflict-free fragment LDS), 2 blocks/SM.
// Dynamic smem: 4 * 128 * 36 * 4B = 72 KB.
// =====================================================================
#define OSTR 36
#define OTILE (BM * OSTR)

__global__ __launch_bounds__(256, 2)
void gemm_tf32(const float* __restrict__ A, const float* __restrict__ B,
               float* __restrict__ C, const float* __restrict__ bias,
               int M, int N, int K)
{
    extern __shared__ float smem[];
    // layout: A0 | A1 | B0 | B1, each OTILE floats

    int tid  = threadIdx.x;
    int warp = tid >> 5, lane = tid & 31;
    int wm   = warp >> 2;
    int wn   = warp & 3;
    int gID  = lane >> 2;
    int tig  = lane & 3;

    int rowBase = blockIdx.x * BM;
    int colBase = blockIdx.y * BN;

    // stage mapping: 2 threads per tile row, each 64B (4 x 16B)
    int srow = tid >> 1;        // 0..127
    int shalf = tid & 1;        // 0..1 (16-float half of BK)
    const float* Asrc = A + (size_t)(rowBase + srow) * K + shalf * 16;
    const float* Bsrc = B + (size_t)(colBase + srow) * K + shalf * 16;
    uint32_t smemBase = (uint32_t)__cvta_generic_to_shared(smem);
    uint32_t aDst = smemBase + (uint32_t)(srow * OSTR + shalf * 16) * 4;
    uint32_t bDst = aDst + 2 * OTILE * 4;

    const int NT = K / BK;

    float acc[4][4][4];
#pragma unroll
    for (int mt = 0; mt < 4; mt++)
#pragma unroll
        for (int nt = 0; nt < 4; nt++)
#pragma unroll
            for (int q = 0; q < 4; q++) acc[mt][nt][q] = 0.f;

    // prologue: stage tile 0 into buffer 0
#pragma unroll
    for (int c = 0; c < 4; c++) {
        cp16(aDst + c * 16, Asrc + c * 4);
        cp16(bDst + c * 16, Bsrc + c * 4);
    }
    asm volatile("cp.async.commit_group;");

    for (int kt = 0; kt < NT; kt++) {
        int cur = kt & 1;
        if (kt + 1 < NT) {
            int nxt = cur ^ 1;
            const float* ap = Asrc + (size_t)(kt + 1) * BK;
            const float* bp = Bsrc + (size_t)(kt + 1) * BK;
            uint32_t ad = aDst + (uint32_t)nxt * OTILE * 4;
            uint32_t bd = bDst + (uint32_t)nxt * OTILE * 4;
#pragma unroll
            for (int c = 0; c < 4; c++) {
                cp16(ad + c * 16, ap + c * 4);
                cp16(bd + c * 16, bp + c * 4);
            }
            asm volatile("cp.async.commit_group;");
            asm volatile("cp.async.wait_group 1;");
        } else {
            asm volatile("cp.async.wait_group 0;");
        }
        __syncthreads();

        const float* sA = smem + cur * OTILE;
        const float* sB = smem + 2 * OTILE + cur * OTILE;

#pragma unroll
        for (int ks = 0; ks < 4; ks++) {
            int kb = ks * 8;
            uint32_t af[4][4];
#pragma unroll
            for (int mt = 0; mt < 4; mt++) {
                int m0 = wm * 64 + mt * 16 + gID;
                af[mt][0] = __float_as_uint(sA[(m0    ) * OSTR + kb + tig    ]);
                af[mt][1] = __float_as_uint(sA[(m0 + 8) * OSTR + kb + tig    ]);
                af[mt][2] = __float_as_uint(sA[(m0    ) * OSTR + kb + tig + 4]);
                af[mt][3] = __float_as_uint(sA[(m0 + 8) * OSTR + kb + tig + 4]);
            }
#pragma unroll
            for (int nt = 0; nt < 4; nt++) {
                int n0 = wn * 32 + nt * 8 + gID;
                uint32_t b0 = __float_as_uint(sB[n0 * OSTR + kb + tig    ]);
                uint32_t b1 = __float_as_uint(sB[n0 * OSTR + kb + tig + 4]);
#pragma unroll
                for (int mt = 0; mt < 4; mt++)
                    mma_tf32(acc[mt][nt], af[mt][0], af[mt][1], af[mt][2],
                             af[mt][3], b0, b1);
            }
        }
        __syncthreads();
    }

#pragma unroll
    for (int mt = 0; mt < 4; mt++) {
#pragma unroll
        for (int nt = 0; nt < 4; nt++) {
            int r0 = rowBase + wm * 64 + mt * 16 + gID;
            int c0 = colBase + wn * 32 + nt * 8 + tig * 2;
            float bi0 = bias ? bias[c0] : 0.f;
            float bi1 = bias ? bias[c0 + 1] : 0.f;
            float* p0 = C + (size_t)r0 * N + c0;
            float* p1 = C + (size_t)(r0 + 8) * N + c0;
            *(float2*)p0 = make_float2(acc[mt][nt][0] + bi0, acc[mt][nt][1] + bi1);
            *(float2*)p1 = make_float2(acc[mt][nt][2] + bi0, acc[mt][nt][3] + bi1);
        }
    }
}

// =====================================================================
// Fused 3-term tf32 split GEMM (near-fp32): C = A*B^T + bias in ONE pass.
// (input projections feed the 128-step recurrence -> keep rna split)
// =====================================================================
__global__ __launch_bounds__(256)
void gemm_split3(const float* __restrict__ A, const float* __restrict__ B,
                 float* __restrict__ C, const float* __restrict__ bias,
                 int M, int N, int K)
{
    extern __shared__ float smem[];
    float* Ah = smem;
    float* Al = smem + BK * SAPAD;
    float* Bh = smem + 2 * BK * SAPAD;
    float* Bl = smem + 3 * BK * SAPAD;

    int tid  = threadIdx.x;
    int warp = tid >> 5, lane = tid & 31;
    int wm   = warp >> 2;
    int wn   = warp & 3;
    int gID  = lane >> 2;
    int tig  = lane & 3;

    int rowBase = blockIdx.x * BM;
    int colBase = blockIdx.y * BN;

    int lc4 = tid & 7;
    int lr  = tid >> 3;
    const float* Aload = A + (size_t)(rowBase + lr) * K + lc4 * 4;
    const float* Bload = B + (size_t)(colBase + lr) * K + lc4 * 4;

    float acc[4][4][4];
#pragma unroll
    for (int mt = 0; mt < 4; mt++)
#pragma unroll
        for (int nt = 0; nt < 4; nt++)
#pragma unroll
            for (int q = 0; q < 4; q++) acc[mt][nt][q] = 0.f;

    const int NT = K / BK;

    for (int kt = 0; kt < NT; kt++) {
#pragma unroll
        for (int i = 0; i < 4; i++) {
            float4 va = *(const float4*)(Aload + (size_t)kt * BK + (size_t)i * 32 * K);
            float4 vb = *(const float4*)(Bload + (size_t)kt * BK + (size_t)i * 32 * K);
            int m = lr + i * 32;
            float a4[4] = {va.x, va.y, va.z, va.w};
            float b4[4] = {vb.x, vb.y, vb.z, vb.w};
#pragma unroll
            for (int q = 0; q < 4; q++) {
                float hi, lo;
                split_cvt(a4[q], hi, lo);
                Ah[(lc4 * 4 + q) * SAPAD + m] = hi;
                Al[(lc4 * 4 + q) * SAPAD + m] = lo;
                split_cvt(b4[q], hi, lo);
                Bh[(lc4 * 4 + q) * SAPAD + m] = hi;
                Bl[(lc4 * 4 + q) * SAPAD + m] = lo;
            }
        }
        __syncthreads();

#pragma unroll
        for (int ks = 0; ks < 4; ks++) {
            int kb = ks * 8;
            uint32_t ah[4][4], al[4][4];
#pragma unroll
            for (int mt = 0; mt < 4; mt++) {
                int m0 = wm * 64 + mt * 16 + gID;
                ah[mt][0] = __float_as_uint(Ah[(kb + tig    ) * SAPAD + m0    ]);
                ah[mt][1] = __float_as_uint(Ah[(kb + tig    ) * SAPAD + m0 + 8]);
                ah[mt][2] = __float_as_uint(Ah[(kb + tig + 4) * SAPAD + m0    ]);
                ah[mt][3] = __float_as_uint(Ah[(kb + tig + 4) * SAPAD + m0 + 8]);
                al[mt][0] = __float_as_uint(Al[(kb + tig    ) * SAPAD + m0    ]);
                al[mt][1] = __float_as_uint(Al[(kb + tig    ) * SAPAD + m0 + 8]);
                al[mt][2] = __float_as_uint(Al[(kb + tig + 4) * SAPAD + m0    ]);
                al[mt][3] = __float_as_uint(Al[(kb + tig + 4) * SAPAD + m0 + 8]);
            }
#pragma unroll
            for (int nt = 0; nt < 4; nt++) {
                int n0 = wn * 32 + nt * 8 + gID;
                uint32_t bh0 = __float_as_uint(Bh[(kb + tig    ) * SAPAD + n0]);
                uint32_t bh1 = __float_as_uint(Bh[(kb + tig + 4) * SAPAD + n0]);
                uint32_t bl0 = __float_as_uint(Bl[(kb + tig    ) * SAPAD + n0]);
                uint32_t bl1 = __float_as_uint(Bl[(kb + tig + 4) * SAPAD + n0]);
#pragma unroll
                for (int mt = 0; mt < 4; mt++) {
                    mma_tf32(acc[mt][nt], ah[mt][0], ah[mt][1], ah[mt][2], ah[mt][3], bh0, bh1);
                    mma_tf32(acc[mt][nt], al[mt][0], al[mt][1], al[mt][2], al[mt][3], bh0, bh1);
                    mma_tf32(acc[mt][nt], ah[mt][0], ah[mt][1], ah[mt][2], ah[mt][3], bl0, bl1);
                }
            }
        }
        __syncthreads();
    }

#pragma unroll
    for (int mt = 0; mt < 4; mt++) {
#pragma unroll
        for (int nt = 0; nt < 4; nt++) {
            int r0 = rowBase + wm * 64 + mt * 16 + gID;
            int c0 = colBase + wn * 32 + nt * 8 + tig * 2;
            float bi0 = bias ? bias[c0] : 0.f;
            float bi1 = bias ? bias[c0 + 1] : 0.f;
            float* p0 = C + (size_t)r0 * N + c0;
            float* p1 = C + (size_t)(r0 + 8) * N + c0;
            *(float2*)p0 = make_float2(acc[mt][nt][0] + bi0, acc[mt][nt][1] + bi1);
            *(float2*)p1 = make_float2(acc[mt][nt][2] + bi0, acc[mt][nt][3] + bi1);
        }
    }
}

// =====================================================================
// Persistent RNN recurrence v3 (proven in R9, unchanged).
// =====================================================================
__device__ __forceinline__ void red_add_release_gpu(int* p, int v)
{
    asm volatile("red.release.gpu.global.add.s32 [%0], %1;" :: "l"(p), "r"(v) : "memory");
}
__device__ __forceinline__ int ld_acquire_int(const int* p)
{
    int v;
    asm volatile("ld.acquire.gpu.global.s32 %0, [%1];" : "=r"(v) : "l"(p) : "memory");
    return v;
}

// transpose hidden[l] [B][H] -> g_h4 buf0 quad layout; reset barrier counter
__global__ __launch_bounds__(256)
void htrans_in_k(const float* __restrict__ hsrc)
{
    if (blockIdx.x == 0 && threadIdx.x == 0) g_ctr = 0;
    int idx = blockIdx.x * 256 + threadIdx.x;   // over 8192 quads
    int q = idx >> 5;          // 0..255  (k-quad)
    int b = idx & 31;
    float4 v = make_float4(hsrc[(size_t)b * HID + q * 4 + 0],
                           hsrc[(size_t)b * HID + q * 4 + 1],
                           hsrc[(size_t)b * HID + q * 4 + 2],
                           hsrc[(size_t)b * HID + q * 4 + 3]);
    g_h4[(size_t)q * BATCH + b] = v;
}

__global__ __launch_bounds__(256)
void rnn_persist(const float* __restrict__ xw,   // [128][32][1024]
                 const float* __restrict__ Whh,  // [1024][1024]
                 const float* __restrict__ bhh,  // [1024]
                 float* __restrict__ yseq)       // [128][32][1024]
{
    __shared__ float swT[HID][8];       // 32 KB: swT[k][j] = Whh[jbase+j][k]
    __shared__ float sb[8];
    __shared__ float red[8][BATCH][8];  // 8 KB partials

    int tid = threadIdx.x;
    int bid = blockIdx.x;
    int jbase = bid * 8;

    // load W slice transposed (coalesced gmem reads)
    for (int idx = tid; idx < 8 * HID; idx += 256) {
        int j = idx >> 10;
        int k = idx & 1023;
        swT[k][j] = Whh[(size_t)(jbase + j) * HID + k];
    }
    if (tid < 8) sb[tid] = bhh[jbase + tid];
    __syncthreads();

    int w    = tid >> 5;        // warp -> k slice
    int lane = tid & 31;        // lane -> batch
    int kqbase = w * 32;        // 32 quads (=128 k) per warp
    int rb = tid >> 3;          // reduce: batch
    int rj = tid & 7;           // reduce: local j
    int jout = jbase + rj;
    int houtOff = ((jout >> 2) * BATCH + rb) * 4 + (jout & 3);

#pragma unroll 1
    for (int t = 0; t < T_LEN; t++) {
        const float4* hcur = g_h4 + (size_t)(t & 1) * (HID / 4) * BATCH;
        float*        hnxt = (float*)(g_h4 + (size_t)((t + 1) & 1) * (HID / 4) * BATCH);

        float xval = xw[(size_t)t * BATCH * HID + (size_t)rb * HID + jout];

        float acc[8];
#pragma unroll
        for (int j = 0; j < 8; j++) acc[j] = 0.f;

        float4 hv[8], hp[8];
#pragma unroll
        for (int i = 0; i < 8; i++)
            hv[i] = __ldcg(hcur + (size_t)(kqbase + i) * BATCH + lane);

#pragma unroll
        for (int c = 0; c < 4; c++) {
            if (c < 3) {
#pragma unroll
                for (int i = 0; i < 8; i++)
                    hp[i] = __ldcg(hcur + (size_t)(kqbase + (c + 1) * 8 + i) * BATCH + lane);
            }
#pragma unroll
            for (int i = 0; i < 8; i++) {
                int k0 = (kqbase + c * 8 + i) * 4;
                float hd[4] = {hv[i].x, hv[i].y, hv[i].z, hv[i].w};
#pragma unroll
                for (int d = 0; d < 4; d++) {
                    float4 wa = *(const float4*)&swT[k0 + d][0];
                    float4 wb = *(const float4*)&swT[k0 + d][4];
                    acc[0] += wa.x * hd[d];
                    acc[1] += wa.y * hd[d];
                    acc[2] += wa.z * hd[d];
                    acc[3] += wa.w * hd[d];
                    acc[4] += wb.x * hd[d];
                    acc[5] += wb.y * hd[d];
                    acc[6] += wb.z * hd[d];
                    acc[7] += wb.w * hd[d];
                }
            }
            if (c < 3) {
#pragma unroll
                for (int i = 0; i < 8; i++) hv[i] = hp[i];
            }
        }

        // cross-warp (k-slice) reduction
        *(float4*)&red[w][lane][0] = make_float4(acc[0], acc[1], acc[2], acc[3]);
        *(float4*)&red[w][lane][4] = make_float4(acc[4], acc[5], acc[6], acc[7]);
        __syncthreads();
        {
            float s = 0.f;
#pragma unroll
            for (int ww = 0; ww < 8; ww++) s += red[ww][rb][rj];
            float v = tanhf(s + sb[rj] + xval);
            __stcg(hnxt + houtOff, v);
            yseq[(size_t)t * BATCH * HID + (size_t)rb * HID + jout] = v;
        }

        // grid barrier (single release-add + single acquire poller + sleep)
        __syncthreads();
        if (tid == 0) {
            red_add_release_gpu(&g_ctr, 1);
            int target = 128 * (t + 1);
            while (ld_acquire_int(&g_ctr) < target) {
                __nanosleep(64);
            }
        }
        __syncthreads();
    }
}

// =====================================================================
// In-place log_softmax over rows of 32000. Row cached in 128 KB smem.
// =====================================================================
__global__ __launch_bounds__(256)
void logsoftmax_k(float* __restrict__ out)
{
    extern __shared__ float srow[];
    __shared__ float red[256];
    int tid = threadIdx.x;
    float4* p4 = (float4*)(out + (size_t)blockIdx.x * VOCAB);

    float m = -3.4e38f;
#pragma unroll 4
    for (int i = tid; i < VOCAB / 4; i += 256) {
        float4 v = p4[i];
        *(float4*)&srow[i * 4] = v;
        m = fmaxf(m, fmaxf(fmaxf(v.x, v.y), fmaxf(v.z, v.w)));
    }
    red[tid] = m; __syncthreads();
    for (int s = 128; s > 0; s >>= 1) {
        if (tid < s) red[tid] = fmaxf(red[tid], red[tid + s]);
        __syncthreads();
    }
    float rm = red[0]; __syncthreads();

    float sum = 0.f;
    for (int i = tid; i < VOCAB; i += 256) sum += expf(srow[i] - rm);
    red[tid] = sum; __syncthreads();
    for (int s = 128; s > 0; s >>= 1) {
        if (tid < s) red[tid] += red[tid + s];
        __syncthreads();
    }
    float lz = rm + logf(red[0]);

    for (int i = tid; i < VOCAB / 4; i += 256) {
        float4 v = *(float4*)&srow[i * 4];
        v.x -= lz; v.y -= lz; v.z -= lz; v.w -= lz;
        p4[i] = v;
    }
}

// =====================================================================
// host orchestration (graph-capturable)
// =====================================================================
extern "C" void kernel_launch(void* const* d_in, const int* in_sizes, int n_in,
                              void* d_out, int out_size)
{
    const int*   input_x = (const int*)  d_in[0];
    const float* hidden  = (const float*)d_in[1];
    const float* emb     = (const float*)d_in[2];
    const float* W_ih    = (const float*)d_in[3];
    const float* W_hh    = (const float*)d_in[4];
    const float* b_ih    = (const float*)d_in[5];
    const float* b_hh    = (const float*)d_in[6];
    const float* W_out   = (const float*)d_in[7];
    const float* b_out   = (const float*)d_in[8];
    float* out = (float*)d_out;

    float *gx, *gxw;
    cudaGetSymbolAddress((void**)&gx,  g_x);
    cudaGetSymbolAddress((void**)&gxw, g_xw);

    cudaFuncSetAttribute(logsoftmax_k,
                         cudaFuncAttributeMaxDynamicSharedMemorySize,
                         VOCAB * (int)sizeof(float));
    cudaFuncSetAttribute(gemm_split3,
                         cudaFuncAttributeMaxDynamicSharedMemorySize,
                         4 * BK * SAPAD * (int)sizeof(float));
    cudaFuncSetAttribute(gemm_tf32,
                         cudaFuncAttributeMaxDynamicSharedMemorySize,
                         4 * OTILE * (int)sizeof(float));

    const int writeHidden = (size_t)out_size >= LOGITS_ELEMS + HIDDEN_ELEMS;

    // 1) embedding gather
    embed_k<<<MROWS, 256>>>(input_x, emb, gx);

    for (int l = 0; l < 2; l++) {
        const float* Wi = W_ih + (size_t)l * HID * HID;
        const float* Wh = W_hh + (size_t)l * HID * HID;
        const float* bi = b_ih + (size_t)l * HID;
        const float* bh = b_hh + (size_t)l * HID;

        // init transposed hidden (buf 0) + reset barrier counter
        htrans_in_k<<<BATCH * HID / 256, 256>>>(hidden + (size_t)l * BATCH * HID);

        // input projection: fused 3-term tf32 split, single launch
        dim3 gp(MROWS / BM, HID / BN);
        gemm_split3<<<gp, 256, 4 * BK * SAPAD * (int)sizeof(float)>>>(
            gx, Wi, gxw, bi, MROWS, HID, HID);

        // persistent recurrence (exact fp32)
        rnn_persist<<<128, 256>>>(gxw, Wh, bh, gx);

        // new_hidden[l] = y[T-1]
        if (writeHidden)
            cudaMemcpyAsync(out + LOGITS_ELEMS + (size_t)l * BATCH * HID,
                            gx + (size_t)(T_LEN - 1) * BATCH * HID,
                            (size_t)BATCH * HID * sizeof(float),
                            cudaMemcpyDeviceToDevice, 0);
    }

    // output projection (cp.async double-buffered HMMA tf32)
    dim3 go(MROWS / BM, VOCAB / BN);
    gemm_tf32<<<go, 256, 4 * OTILE * (int)sizeof(float)>>>(
        gx, W_out, out, b_out, MROWS, VOCAB, HID);

    // in-place log_softmax
    logsoftmax_k<<<MROWS, 256, VOCAB * (int)sizeof(float)>>>(out);
}